// round 13
// baseline (speedup 1.0000x reference)
#include <cuda_runtime.h>
#include <cuda_bf16.h>
#include <math.h>
#include <stdint.h>

#define B_      2
#define CIN     48
#define HH      512
#define WW      512
#define HW      (512*512)
#define CQ      144
#define HEADS   8
#define CSUB    6
#define NB      4
#define H1      128
#define NTOK    16384
#define CB      96
#define NCHUNK  16
#define BHTOT   16

typedef unsigned long long u64;

__device__ __forceinline__ uint32_t cvta(const void* p) {
    return (uint32_t)__cvta_generic_to_shared(p);
}
__device__ __forceinline__ void ldsm_x4(uint32_t* r, uint32_t a) {
    asm volatile("ldmatrix.sync.aligned.m8n8.x4.shared.b16 {%0,%1,%2,%3}, [%4];"
        : "=r"(r[0]), "=r"(r[1]), "=r"(r[2]), "=r"(r[3]) : "r"(a));
}
__device__ __forceinline__ void ldsm_x2(uint32_t* r, uint32_t a) {
    asm volatile("ldmatrix.sync.aligned.m8n8.x2.shared.b16 {%0,%1}, [%2];"
        : "=r"(r[0]), "=r"(r[1]) : "r"(a));
}
__device__ __forceinline__ void ldsm_x2t(uint32_t* r, uint32_t a) {
    asm volatile("ldmatrix.sync.aligned.m8n8.x2.trans.shared.b16 {%0,%1}, [%2];"
        : "=r"(r[0]), "=r"(r[1]) : "r"(a));
}
__device__ __forceinline__ void mma_bf16(float* c, const uint32_t* a, const uint32_t* b) {
    asm volatile("mma.sync.aligned.m16n8k16.row.col.f32.bf16.bf16.f32 "
        "{%0,%1,%2,%3}, {%4,%5,%6,%7}, {%8,%9}, {%0,%1,%2,%3};"
        : "+f"(c[0]), "+f"(c[1]), "+f"(c[2]), "+f"(c[3])
        : "r"(a[0]), "r"(a[1]), "r"(a[2]), "r"(a[3]), "r"(b[0]), "r"(b[1]));
}
__device__ __forceinline__ void split4(float4 v, u64& hi, u64& lo) {
    __nv_bfloat16 h0 = __float2bfloat16(v.x), h1 = __float2bfloat16(v.y),
                  h2 = __float2bfloat16(v.z), h3 = __float2bfloat16(v.w);
    union { __nv_bfloat16 h[4]; u64 u; } a, c;
    a.h[0] = h0; a.h[1] = h1; a.h[2] = h2; a.h[3] = h3;
    c.h[0] = __float2bfloat16(v.x - __bfloat162float(h0));
    c.h[1] = __float2bfloat16(v.y - __bfloat162float(h1));
    c.h[2] = __float2bfloat16(v.z - __bfloat162float(h2));
    c.h[3] = __float2bfloat16(v.w - __bfloat162float(h3));
    hi = a.u; lo = c.u;
}

// ---------------- scratch ----------------
__device__ float g_q [(size_t)BHTOT*CB*NTOK];
__device__ float g_k [(size_t)BHTOT*CB*NTOK];
__device__ float g_v [(size_t)BHTOT*CB*NTOK];
__device__ float g_Spart[(size_t)BHTOT*NCHUNK*CB*CB];
__device__ float g_ssqpart[2*BHTOT*NCHUNK*CB];
__device__ float g_attn[(size_t)BHTOT*CB*CB];
__device__ float g_out1[(size_t)B_*CIN*HW];

// ---------------- K1: fused 1x1 qkv conv (bf16-split mma) + 3x3 depthwise + scatter ----
// grid (16, 64, B), block 512. Tile 32x8 outputs, halo 34x10 = 340 px.
// Dynamic smem layout (bytes):
#define FS_XH 0
#define FS_XL 37632
#define FS_WH 75264
#define FS_WL 91392
#define FS_DW 107520
#define FS_QS 112704
#define FS_TOTAL 187968
__global__ void __launch_bounds__(512, 1) k_fused(const float* __restrict__ xg,
                                                  const float* __restrict__ wq,
                                                  const float* __restrict__ dwW) {
    extern __shared__ char smp[];
    __nv_bfloat16* Xh = (__nv_bfloat16*)(smp + FS_XH);   // [48][392]
    __nv_bfloat16* Xl = (__nv_bfloat16*)(smp + FS_XL);
    __nv_bfloat16* Wh = (__nv_bfloat16*)(smp + FS_WH);   // [144][56]
    __nv_bfloat16* Wl = (__nv_bfloat16*)(smp + FS_WL);
    float* dws = (float*)(smp + FS_DW);                  // [144][9]
    float* Qs  = (float*)(smp + FS_QS);                  // [48][392] fp32
    const int x0 = blockIdx.x * 32, y0 = blockIdx.y * 8, b = blockIdx.z;
    const int tid = threadIdx.x, lane = tid & 31, w = tid >> 5;   // 16 warps

    // load x halo (zero outside image), bf16 hi/lo split
    const float* xb = xg + (size_t)b*CIN*HW;
    for (int i = tid; i < 48*340; i += 512) {
        int ic = i / 340, p = i % 340;
        int hy = p / 34, hx = p % 34;
        int gy = y0 - 1 + hy, gx = x0 - 1 + hx;
        float v = 0.f;
        if (gy >= 0 && gy < HH && gx >= 0 && gx < WW) v = xb[(size_t)ic*HW + gy*WW + gx];
        __nv_bfloat16 h = __float2bfloat16(v);
        Xh[ic*392 + p] = h;
        Xl[ic*392 + p] = __float2bfloat16(v - __bfloat162float(h));
    }
    for (int i = tid; i < 144*48; i += 512) {
        int oc = i / 48, ic = i % 48;
        float v = wq[oc*48 + ic];
        __nv_bfloat16 h = __float2bfloat16(v);
        Wh[oc*56 + ic] = h;
        Wl[oc*56 + ic] = __float2bfloat16(v - __bfloat162float(h));
    }
    for (int i = tid; i < 144*9; i += 512) dws[i] = dwW[i];
    __syncthreads();

    const int n0 = w * 24;   // warp's 24-col slice of N=384 (padded; cols >=340 junk, discarded)
    for (int pt = 0; pt < 3; ++pt) {
        float acc[3][3][4];
#pragma unroll
        for (int f = 0; f < 3; ++f)
#pragma unroll
            for (int g = 0; g < 3; ++g)
#pragma unroll
                for (int t = 0; t < 4; ++t) acc[f][g][t] = 0.f;
#pragma unroll
        for (int ks = 0; ks < 3; ++ks) {
            uint32_t ah[3][4], al[3][4], bhf[3][2], blf[3][2];
            const int arow = lane & 15, acol = ks*16 + ((lane >> 4) << 3);
#pragma unroll
            for (int f = 0; f < 3; ++f) {
                int off = (pt*48 + f*16 + arow)*56 + acol;
                ldsm_x4(ah[f], cvta(&Wh[off]));
                ldsm_x4(al[f], cvta(&Wl[off]));
            }
            const int brow = ks*16 + (lane & 15);
#pragma unroll
            for (int g = 0; g < 3; ++g) {
                int off = brow*392 + n0 + g*8;
                ldsm_x2t(bhf[g], cvta(&Xh[off]));
                ldsm_x2t(blf[g], cvta(&Xl[off]));
            }
#pragma unroll
            for (int f = 0; f < 3; ++f)
#pragma unroll
                for (int g = 0; g < 3; ++g) {
                    mma_bf16(acc[f][g], ah[f], bhf[g]);
                    mma_bf16(acc[f][g], ah[f], blf[g]);
                    mma_bf16(acc[f][g], al[f], bhf[g]);
                }
        }
        __syncthreads();   // previous part's dw reads of Qs complete
#pragma unroll
        for (int f = 0; f < 3; ++f) {
            int row0 = f*16 + (lane >> 2);
#pragma unroll
            for (int g = 0; g < 3; ++g) {
                int col = n0 + g*8 + (lane & 3)*2;
                *(float2*)&Qs[row0*392 + col]     = make_float2(acc[f][g][0], acc[f][g][1]);
                *(float2*)&Qs[(row0+8)*392 + col] = make_float2(acc[f][g][2], acc[f][g][3]);
            }
        }
        __syncthreads();
        // 3x3 depthwise on Qs halo + scatter to block layout
        float* dstbase = (pt == 0) ? g_q : (pt == 1) ? g_k : g_v;
        for (int o = tid; o < 48*256; o += 512) {
            int ch = o >> 8, p = o & 255;
            int ly = p >> 5, lx = p & 31;
            const float* wd = &dws[(pt*48 + ch)*9];
            const float* q = &Qs[ch*392 + ly*34 + lx];
            float s = 0.f;
#pragma unroll
            for (int dy = 0; dy < 3; ++dy)
#pragma unroll
                for (int dx = 0; dx < 3; ++dx)
                    s = fmaf(wd[dy*3 + dx], q[dy*34 + dx], s);
            int y = y0 + ly, xg2 = x0 + lx;
            int head = ch / CSUB, ci = ch % CSUB;
            int row = ci*16 + (y & 3)*4 + (xg2 & 3);
            int n   = (y >> 2)*H1 + (xg2 >> 2);
            dstbase[((size_t)(b*HEADS + head)*CB + row)*NTOK + n] = s;
        }
    }
}

// ---------------- K6: 1x1 proj conv as bf16-split mma (validated R11) ----------------
__global__ void __launch_bounds__(256, 2) k_conv(const float* __restrict__ wg,
                                                 float* __restrict__ dst_io) {
    __shared__ __nv_bfloat16 Xh[48*264], Xl[48*264];
    __shared__ __nv_bfloat16 Wh[48*56],  Wl[48*56];
    const float* xg = (const float*)g_out1;
    float* dst = dst_io;
    const int px0 = blockIdx.y * 256;
    const int b   = blockIdx.z;
    const int tid = threadIdx.x, lane = tid & 31, w = tid >> 5;

    const float* xb = xg + (size_t)b*48*HW + px0;
    float4 xs[12];
#pragma unroll
    for (int t = 0; t < 12; ++t) {
        int i = tid + t*256;
        int r = i >> 6, c4 = (i & 63) * 4;
        xs[t] = *(const float4*)&xb[(size_t)r*HW + c4];
    }
    float ws[9];
#pragma unroll
    for (int t = 0; t < 9; ++t) {
        int i = tid + t*256;
        ws[t] = wg[(i/48)*48 + (i%48)];
    }
#pragma unroll
    for (int t = 0; t < 12; ++t) {
        int i = tid + t*256;
        int r = i >> 6, c4 = (i & 63) * 4;
        u64 hi, lo; split4(xs[t], hi, lo);
        *(u64*)&Xh[r*264 + c4] = hi;
        *(u64*)&Xl[r*264 + c4] = lo;
    }
#pragma unroll
    for (int t = 0; t < 9; ++t) {
        int i = tid + t*256;
        int oc = i/48, ic = i%48;
        __nv_bfloat16 h = __float2bfloat16(ws[t]);
        Wh[oc*56 + ic] = h;
        Wl[oc*56 + ic] = __float2bfloat16(ws[t] - __bfloat162float(h));
    }
    __syncthreads();

    float acc[3][4][4];
#pragma unroll
    for (int f = 0; f < 3; ++f)
#pragma unroll
        for (int g = 0; g < 4; ++g)
#pragma unroll
            for (int t = 0; t < 4; ++t) acc[f][g][t] = 0.f;

    const int n0 = w * 32;
#pragma unroll
    for (int ks = 0; ks < 3; ++ks) {
        uint32_t ah[3][4], al[3][4], bhf[4][2], blf[4][2];
        const int arow = lane & 15, acol = ks*16 + ((lane >> 4) << 3);
#pragma unroll
        for (int f = 0; f < 3; ++f) {
            int off = (f*16 + arow)*56 + acol;
            ldsm_x4(ah[f], cvta(&Wh[off]));
            ldsm_x4(al[f], cvta(&Wl[off]));
        }
        const int brow = ks*16 + (lane & 15);
#pragma unroll
        for (int g = 0; g < 4; ++g) {
            int off = brow*264 + n0 + g*8;
            ldsm_x2t(bhf[g], cvta(&Xh[off]));
            ldsm_x2t(blf[g], cvta(&Xl[off]));
        }
#pragma unroll
        for (int f = 0; f < 3; ++f)
#pragma unroll
            for (int g = 0; g < 4; ++g) {
                mma_bf16(acc[f][g], ah[f], bhf[g]);
                mma_bf16(acc[f][g], ah[f], blf[g]);
                mma_bf16(acc[f][g], al[f], bhf[g]);
            }
    }
#pragma unroll
    for (int f = 0; f < 3; ++f) {
        int row0 = f*16 + (lane >> 2);
#pragma unroll
        for (int g = 0; g < 4; ++g) {
            int col = px0 + n0 + g*8 + (lane & 3)*2;
            *(float2*)&dst[((size_t)b*CIN + row0)*HW + col]     = make_float2(acc[f][g][0], acc[f][g][1]);
            *(float2*)&dst[((size_t)b*CIN + row0 + 8)*HW + col] = make_float2(acc[f][g][2], acc[f][g][3]);
        }
    }
}

// ---------------- K3: gram via mma.sync bf16 hi/lo split (validated R6) ----------------
#define GP 40
__global__ void __launch_bounds__(256, 2) k_gram() {
    __shared__ __nv_bfloat16 Qh[96*GP], Ql[96*GP], Kh[96*GP], Kl[96*GP];
    const int chunk = blockIdx.x, bh = blockIdx.y;
    const int tid = threadIdx.x, lane = tid & 31, w = tid >> 5;
    const int wm = w >> 2, wn = w & 3;
    const int n0 = chunk * (NTOK / NCHUNK);

    const float* Q  = g_q + (size_t)bh*CB*NTOK;
    const float* Kp = g_k + (size_t)bh*CB*NTOK;

    float acc[9][4];
#pragma unroll
    for (int t = 0; t < 9; ++t) { acc[t][0]=0.f; acc[t][1]=0.f; acc[t][2]=0.f; acc[t][3]=0.f; }
    float sq[12], sk[12];
#pragma unroll
    for (int t = 0; t < 12; ++t) { sq[t] = 0.f; sk[t] = 0.f; }

    float qr[12], kr[12];
#pragma unroll
    for (int t = 0; t < 12; ++t) {
        int r = w + 8*t;
        qr[t] = Q [(size_t)r*NTOK + n0 + lane];
        kr[t] = Kp[(size_t)r*NTOK + n0 + lane];
    }

    const int NIT = (NTOK / NCHUNK) / 32;
    for (int kt = 0; kt < NIT; ++kt) {
        __syncthreads();
#pragma unroll
        for (int t = 0; t < 12; ++t) {
            int r = w + 8*t;
            float qv = qr[t], kv = kr[t];
            __nv_bfloat16 qh = __float2bfloat16(qv);
            __nv_bfloat16 kh = __float2bfloat16(kv);
            Qh[r*GP + lane] = qh;
            Ql[r*GP + lane] = __float2bfloat16(qv - __bfloat162float(qh));
            Kh[r*GP + lane] = kh;
            Kl[r*GP + lane] = __float2bfloat16(kv - __bfloat162float(kh));
            sq[t] = fmaf(qv, qv, sq[t]);
            sk[t] = fmaf(kv, kv, sk[t]);
        }
        __syncthreads();
        if (kt + 1 < NIT) {
            int base = n0 + (kt + 1)*32 + lane;
#pragma unroll
            for (int t = 0; t < 12; ++t) {
                int r = w + 8*t;
                qr[t] = Q [(size_t)r*NTOK + base];
                kr[t] = Kp[(size_t)r*NTOK + base];
            }
        }
#pragma unroll
        for (int ks = 0; ks < 2; ++ks) {
            const int k0 = ks*16;
            uint32_t ah[3][4], al[3][4], bhF[3][2], blF[3][2];
            const int arow = (lane & 15), acol = k0 + ((lane >> 4) << 3);
            const int brow = (lane & 7),  bcol = k0 + (((lane >> 3) & 1) << 3);
#pragma unroll
            for (int f = 0; f < 3; ++f) {
                int off = (wm*48 + f*16 + arow)*GP + acol;
                ldsm_x4(ah[f], cvta(&Qh[off]));
                ldsm_x4(al[f], cvta(&Ql[off]));
            }
#pragma unroll
            for (int g = 0; g < 3; ++g) {
                int off = (wn*24 + g*8 + brow)*GP + bcol;
                ldsm_x2(bhF[g], cvta(&Kh[off]));
                ldsm_x2(blF[g], cvta(&Kl[off]));
            }
#pragma unroll
            for (int f = 0; f < 3; ++f)
#pragma unroll
                for (int g = 0; g < 3; ++g) {
                    mma_bf16(acc[f*3+g], ah[f], bhF[g]);
                    mma_bf16(acc[f*3+g], ah[f], blF[g]);
                    mma_bf16(acc[f*3+g], al[f], bhF[g]);
                }
        }
    }
    float* Sp = g_Spart + ((size_t)bh*NCHUNK + chunk)*CB*CB;
#pragma unroll
    for (int f = 0; f < 3; ++f)
#pragma unroll
        for (int g = 0; g < 3; ++g) {
            int row = wm*48 + f*16 + (lane >> 2);
            int col = wn*24 + g*8 + (lane & 3)*2;
            float* c = acc[f*3+g];
            *(float2*)&Sp[row*CB + col]     = make_float2(c[0], c[1]);
            *(float2*)&Sp[(row+8)*CB + col] = make_float2(c[2], c[3]);
        }
#pragma unroll
    for (int t = 0; t < 12; ++t) {
        float s1 = sq[t], s2 = sk[t];
#pragma unroll
        for (int off = 16; off > 0; off >>= 1) {
            s1 += __shfl_xor_sync(0xffffffffu, s1, off);
            s2 += __shfl_xor_sync(0xffffffffu, s2, off);
        }
        if (lane == 0) {
            int r = w + 8*t;
            g_ssqpart[((0*BHTOT + bh)*NCHUNK + chunk)*CB + r] = s1;
            g_ssqpart[((1*BHTOT + bh)*NCHUNK + chunk)*CB + r] = s2;
        }
    }
}

// ---------------- K4: reduce + normalize + softmax ----------------
__global__ void k_soft(const float* __restrict__ temperature) {
    __shared__ float invk[96];
    __shared__ float invq[8];
    const int bh = blockIdx.y;
    const int rb = blockIdx.x * 8;
    const int head = bh & 7;
    const int tid = threadIdx.x;
    const int lane = tid & 31;
    const int w = tid >> 5;

    if (tid < 96) {
        float sumk = 0.f;
        for (int c = 0; c < NCHUNK; ++c)
            sumk += g_ssqpart[((1*BHTOT + bh)*NCHUNK + c)*CB + tid];
        invk[tid] = 1.f / fmaxf(sqrtf(sumk), 1e-12f);
    } else if (tid >= 128 && tid < 136) {
        int r = rb + tid - 128;
        float sumq = 0.f;
        for (int c = 0; c < NCHUNK; ++c)
            sumq += g_ssqpart[((0*BHTOT + bh)*NCHUNK + c)*CB + r];
        invq[tid - 128] = 1.f / fmaxf(sqrtf(sumq), 1e-12f);
    }
    __syncthreads();
    const float temp = temperature[head];
    const float* Sp = g_Spart + (size_t)bh*NCHUNK*CB*CB;
    float* Ao = g_attn + (size_t)bh*CB*CB;

    const int row = rb + w;
    float v[3];
#pragma unroll
    for (int j = 0; j < 3; ++j) {
        int col = lane + 32*j;
        float s = 0.f;
        for (int c = 0; c < NCHUNK; ++c) s += Sp[c*CB*CB + row*CB + col];
        v[j] = s * temp * invq[w] * invk[col];
    }
    float m = fmaxf(v[0], fmaxf(v[1], v[2]));
#pragma unroll
    for (int off = 16; off > 0; off >>= 1) m = fmaxf(m, __shfl_xor_sync(0xffffffffu, m, off));
    float e[3], sum = 0.f;
#pragma unroll
    for (int j = 0; j < 3; ++j) { e[j] = __expf(v[j] - m); sum += e[j]; }
#pragma unroll
    for (int off = 16; off > 0; off >>= 1) sum += __shfl_xor_sync(0xffffffffu, sum, off);
    float inv = 1.f / sum;
#pragma unroll
    for (int j = 0; j < 3; ++j) Ao[row*CB + lane + 32*j] = e[j] * inv;
}

// ---------------- K5: out = attn @ v via bf16-split mma, smem-staged scatter ----------------
__global__ void __launch_bounds__(256, 2) k_av() {
    __shared__ __align__(16) char pool[92160];
    __nv_bfloat16* Ah = (__nv_bfloat16*)pool;
    __nv_bfloat16* Al = (__nv_bfloat16*)(pool + 19968);
    __nv_bfloat16* Vh = (__nv_bfloat16*)(pool + 39936);
    __nv_bfloat16* Vl = (__nv_bfloat16*)(pool + 66048);
    float* Os = (float*)(pool + 39936);
    const int nt = blockIdx.x, bh = blockIdx.y;
    const int b = bh >> 3, head = bh & 7;
    const int tid = threadIdx.x, lane = tid & 31, w = tid >> 5;
    const int wm = w >> 2, wn = w & 3;

    const float* A = g_attn + (size_t)bh*CB*CB;
    const float* V = g_v + (size_t)bh*CB*NTOK + nt*128;
    float4 as[9], vs[12];
#pragma unroll
    for (int t = 0; t < 9; ++t) {
        int i = tid + t*256;
        int r = i / 24, c = (i % 24) * 4;
        as[t] = *(const float4*)&A[r*CB + c];
    }
#pragma unroll
    for (int t = 0; t < 12; ++t) {
        int i = tid + t*256;
        int r = i >> 5, c4 = (i & 31) * 4;
        vs[t] = *(const float4*)&V[(size_t)r*NTOK + c4];
    }
#pragma unroll
    for (int t = 0; t < 9; ++t) {
        int i = tid + t*256;
        int r = i / 24, c = (i % 24) * 4;
        u64 hi, lo; split4(as[t], hi, lo);
        *(u64*)&Ah[r*104 + c] = hi;
        *(u64*)&Al[r*104 + c] = lo;
    }
#pragma unroll
    for (int t = 0; t < 12; ++t) {
        int i = tid + t*256;
        int r = i >> 5, c4 = (i & 31) * 4;
        u64 hi, lo; split4(vs[t], hi, lo);
        *(u64*)&Vh[r*136 + c4] = hi;
        *(u64*)&Vl[r*136 + c4] = lo;
    }
    __syncthreads();

    float acc[3][4][4];
#pragma unroll
    for (int f = 0; f < 3; ++f)
#pragma unroll
        for (int g = 0; g < 4; ++g)
#pragma unroll
            for (int t = 0; t < 4; ++t) acc[f][g][t] = 0.f;

#pragma unroll
    for (int ks = 0; ks < 6; ++ks) {
        uint32_t ah[3][4], al[3][4], bhf[4][2], blf[4][2];
        const int arow = lane & 15, acol = ks*16 + ((lane >> 4) << 3);
#pragma unroll
        for (int f = 0; f < 3; ++f) {
            int off = (wm*48 + f*16 + arow)*104 + acol;
            ldsm_x4(ah[f], cvta(&Ah[off]));
            ldsm_x4(al[f], cvta(&Al[off]));
        }
        const int brow = ks*16 + (lane & 15);
#pragma unroll
        for (int g = 0; g < 4; ++g) {
            int off = brow*136 + wn*32 + g*8;
            ldsm_x2t(bhf[g], cvta(&Vh[off]));
            ldsm_x2t(blf[g], cvta(&Vl[off]));
        }
#pragma unroll
        for (int f = 0; f < 3; ++f)
#pragma unroll
            for (int g = 0; g < 4; ++g) {
                mma_bf16(acc[f][g], ah[f], bhf[g]);
                mma_bf16(acc[f][g], ah[f], blf[g]);
                mma_bf16(acc[f][g], al[f], bhf[g]);
            }
    }
    __syncthreads();
#pragma unroll
    for (int f = 0; f < 3; ++f) {
        int row0 = wm*48 + f*16 + (lane >> 2);
#pragma unroll
        for (int g = 0; g < 4; ++g) {
            int col = wn*32 + g*8 + (lane & 3)*2;
            *(float2*)&Os[row0*132 + col]     = make_float2(acc[f][g][0], acc[f][g][1]);
            *(float2*)&Os[(row0+8)*132 + col] = make_float2(acc[f][g][2], acc[f][g][3]);
        }
    }
    __syncthreads();
    float* outb = g_out1 + (size_t)b*CIN*HW;
    for (int i = tid; i < 24*128; i += 256) {
        int group = i >> 7, n = i & 127;
        int ci = group >> 2, Nh = group & 3;
        int cb = ci*16 + Nh*4;
        float4 val = make_float4(Os[cb*132 + n], Os[(cb+1)*132 + n],
                                 Os[(cb+2)*132 + n], Os[(cb+3)*132 + n]);
        int ch = head*CSUB + ci;
        int y = nt*4 + Nh;
        *(float4*)&outb[((size_t)ch*HH + y)*WW + n*4] = val;
    }
}

// ---------------- launch ----------------
extern "C" void kernel_launch(void* const* d_in, const int* in_sizes, int n_in,
                              void* d_out, int out_size) {
    (void)in_sizes; (void)n_in; (void)out_size;
    const float* x      = (const float*)d_in[0];
    const float* qkv_w  = (const float*)d_in[1];
    const float* dw_w   = (const float*)d_in[2];
    const float* proj_w = (const float*)d_in[3];
    const float* temper = (const float*)d_in[4];
    float* out = (float*)d_out;

    static int smem_set = 0;
    if (!smem_set) {
        cudaFuncSetAttribute(k_fused, cudaFuncAttributeMaxDynamicSharedMemorySize, FS_TOTAL);
        smem_set = 1;
    }

    k_fused<<<dim3(16, 64, B_), 512, FS_TOTAL>>>(x, qkv_w, dw_w);
    k_gram<<<dim3(NCHUNK, BHTOT), 256>>>();
    k_soft<<<dim3(12, BHTOT), 256>>>(temper);
    k_av  <<<dim3(128, BHTOT), 256>>>();
    k_conv<<<dim3(1, HW/256, B_), 256>>>(proj_w, out);
}

// round 15
// speedup vs baseline: 1.1344x; 1.1344x over previous
#include <cuda_runtime.h>
#include <cuda_bf16.h>
#include <math.h>
#include <stdint.h>

#define B_      2
#define CIN     48
#define HH      512
#define WW      512
#define HW      (512*512)
#define CQ      144
#define HEADS   8
#define CSUB    6
#define NB      4
#define H1      128
#define NTOK    16384
#define CB      96
#define NCHUNK  16
#define BHTOT   16

typedef unsigned long long u64;

__device__ __forceinline__ uint32_t cvta(const void* p) {
    return (uint32_t)__cvta_generic_to_shared(p);
}
__device__ __forceinline__ void ldsm_x4(uint32_t* r, uint32_t a) {
    asm volatile("ldmatrix.sync.aligned.m8n8.x4.shared.b16 {%0,%1,%2,%3}, [%4];"
        : "=r"(r[0]), "=r"(r[1]), "=r"(r[2]), "=r"(r[3]) : "r"(a));
}
__device__ __forceinline__ void ldsm_x2(uint32_t* r, uint32_t a) {
    asm volatile("ldmatrix.sync.aligned.m8n8.x2.shared.b16 {%0,%1}, [%2];"
        : "=r"(r[0]), "=r"(r[1]) : "r"(a));
}
__device__ __forceinline__ void ldsm_x2t(uint32_t* r, uint32_t a) {
    asm volatile("ldmatrix.sync.aligned.m8n8.x2.trans.shared.b16 {%0,%1}, [%2];"
        : "=r"(r[0]), "=r"(r[1]) : "r"(a));
}
__device__ __forceinline__ void mma_bf16(float* c, const uint32_t* a, const uint32_t* b) {
    asm volatile("mma.sync.aligned.m16n8k16.row.col.f32.bf16.bf16.f32 "
        "{%0,%1,%2,%3}, {%4,%5,%6,%7}, {%8,%9}, {%0,%1,%2,%3};"
        : "+f"(c[0]), "+f"(c[1]), "+f"(c[2]), "+f"(c[3])
        : "r"(a[0]), "r"(a[1]), "r"(a[2]), "r"(a[3]), "r"(b[0]), "r"(b[1]));
}
__device__ __forceinline__ void split4(float4 v, u64& hi, u64& lo) {
    __nv_bfloat16 h0 = __float2bfloat16(v.x), h1 = __float2bfloat16(v.y),
                  h2 = __float2bfloat16(v.z), h3 = __float2bfloat16(v.w);
    union { __nv_bfloat16 h[4]; u64 u; } a, c;
    a.h[0] = h0; a.h[1] = h1; a.h[2] = h2; a.h[3] = h3;
    c.h[0] = __float2bfloat16(v.x - __bfloat162float(h0));
    c.h[1] = __float2bfloat16(v.y - __bfloat162float(h1));
    c.h[2] = __float2bfloat16(v.z - __bfloat162float(h2));
    c.h[3] = __float2bfloat16(v.w - __bfloat162float(h3));
    hi = a.u; lo = c.u;
}

// ---------------- scratch ----------------
__device__ float g_qkv[(size_t)B_*CQ*HW];
__device__ float g_q [(size_t)BHTOT*CB*NTOK];
__device__ float g_k [(size_t)BHTOT*CB*NTOK];
__device__ float g_v [(size_t)BHTOT*CB*NTOK];
__device__ float g_Spart[(size_t)BHTOT*NCHUNK*CB*CB];
__device__ float g_ssqpart[2*BHTOT*NCHUNK*CB];
__device__ float g_attn[(size_t)BHTOT*CB*CB];
__device__ float g_out1[(size_t)B_*CIN*HW];

// ---------------- K1/K6: 1x1 conv as bf16-split mma GEMM (validated R11) ----------------
// mode 0: src = xg_in, dst = g_qkv. mode 1: src = g_out1, dst = dst_io (harness out).
__global__ void __launch_bounds__(256, 2) k_conv(const float* __restrict__ xg_in,
                                                 const float* __restrict__ wg,
                                                 float* __restrict__ dst_io,
                                                 int nc_out, int mode) {
    __shared__ __nv_bfloat16 Xh[48*264], Xl[48*264];
    __shared__ __nv_bfloat16 Wh[48*56],  Wl[48*56];
    const float* xg = (mode == 0) ? xg_in : (const float*)g_out1;
    float* dst      = (mode == 0) ? (float*)g_qkv : dst_io;
    const int oc0 = blockIdx.x * 48;
    const int px0 = blockIdx.y * 256;
    const int b   = blockIdx.z;
    const int tid = threadIdx.x, lane = tid & 31, w = tid >> 5;

    const float* xb = xg + (size_t)b*48*HW + px0;
    float4 xs[12];
#pragma unroll
    for (int t = 0; t < 12; ++t) {
        int i = tid + t*256;
        int r = i >> 6, c4 = (i & 63) * 4;
        xs[t] = *(const float4*)&xb[(size_t)r*HW + c4];
    }
    float ws[9];
#pragma unroll
    for (int t = 0; t < 9; ++t) {
        int i = tid + t*256;
        ws[t] = wg[(oc0 + i/48)*48 + (i%48)];
    }
#pragma unroll
    for (int t = 0; t < 12; ++t) {
        int i = tid + t*256;
        int r = i >> 6, c4 = (i & 63) * 4;
        u64 hi, lo; split4(xs[t], hi, lo);
        *(u64*)&Xh[r*264 + c4] = hi;
        *(u64*)&Xl[r*264 + c4] = lo;
    }
#pragma unroll
    for (int t = 0; t < 9; ++t) {
        int i = tid + t*256;
        int oc = i/48, ic = i%48;
        __nv_bfloat16 h = __float2bfloat16(ws[t]);
        Wh[oc*56 + ic] = h;
        Wl[oc*56 + ic] = __float2bfloat16(ws[t] - __bfloat162float(h));
    }
    __syncthreads();

    float acc[3][4][4];
#pragma unroll
    for (int f = 0; f < 3; ++f)
#pragma unroll
        for (int g = 0; g < 4; ++g)
#pragma unroll
            for (int t = 0; t < 4; ++t) acc[f][g][t] = 0.f;

    const int n0 = w * 32;
#pragma unroll
    for (int ks = 0; ks < 3; ++ks) {
        uint32_t ah[3][4], al[3][4], bhf[4][2], blf[4][2];
        const int arow = lane & 15, acol = ks*16 + ((lane >> 4) << 3);
#pragma unroll
        for (int f = 0; f < 3; ++f) {
            int off = (f*16 + arow)*56 + acol;
            ldsm_x4(ah[f], cvta(&Wh[off]));
            ldsm_x4(al[f], cvta(&Wl[off]));
        }
        const int brow = ks*16 + (lane & 15);
#pragma unroll
        for (int g = 0; g < 4; ++g) {
            int off = brow*264 + n0 + g*8;
            ldsm_x2t(bhf[g], cvta(&Xh[off]));
            ldsm_x2t(blf[g], cvta(&Xl[off]));
        }
#pragma unroll
        for (int f = 0; f < 3; ++f)
#pragma unroll
            for (int g = 0; g < 4; ++g) {
                mma_bf16(acc[f][g], ah[f], bhf[g]);
                mma_bf16(acc[f][g], ah[f], blf[g]);
                mma_bf16(acc[f][g], al[f], bhf[g]);
            }
    }
#pragma unroll
    for (int f = 0; f < 3; ++f) {
        int row0 = oc0 + f*16 + (lane >> 2);
#pragma unroll
        for (int g = 0; g < 4; ++g) {
            int col = px0 + n0 + g*8 + (lane & 3)*2;
            *(float2*)&dst[((size_t)b*nc_out + row0)*HW + col]     = make_float2(acc[f][g][0], acc[f][g][1]);
            *(float2*)&dst[((size_t)b*nc_out + row0 + 8)*HW + col] = make_float2(acc[f][g][2], acc[f][g][3]);
        }
    }
}

// ---------------- K2: 3x3 depthwise + block scatter (validated R4) ----------------
__global__ void k_dw(const float* __restrict__ dw) {
    __shared__ float tile[34][66];
    const int ch = blockIdx.z % CQ;
    const int b  = blockIdx.z / CQ;
    const int y0 = blockIdx.y * 32;
    const int x0 = blockIdx.x * 64;
    const int tid = threadIdx.x;

    const float* src = g_qkv + ((size_t)b*CQ + ch)*HW;
    for (int i = tid; i < 34*66; i += 256) {
        int yy = i / 66 - 1 + y0;
        int xx = i % 66 - 1 + x0;
        float v = 0.f;
        if (yy >= 0 && yy < HH && xx >= 0 && xx < WW) v = src[yy*WW + xx];
        tile[i/66][i%66] = v;
    }
    float w[9];
#pragma unroll
    for (int t = 0; t < 9; ++t) w[t] = dw[ch*9 + t];
    __syncthreads();

    const int part = ch / 48;
    const int chh  = ch % 48;
    const int head = chh / CSUB;
    const int ci   = chh % CSUB;
    float* base = (part == 0) ? g_q : (part == 1) ? g_k : g_v;
    float* dst = base + (size_t)(b*HEADS + head)*CB*NTOK;

    for (int p = tid; p < 64*32; p += 256) {
        int ly = p >> 6, lx = p & 63;
        float s = 0.f;
#pragma unroll
        for (int dy = 0; dy < 3; ++dy)
#pragma unroll
            for (int dx = 0; dx < 3; ++dx)
                s = fmaf(w[dy*3 + dx], tile[ly + dy][lx + dx], s);
        int y = y0 + ly, xg = x0 + lx;
        int row = ci*16 + (y & 3)*4 + (xg & 3);
        int n   = (y >> 2)*H1 + (xg >> 2);
        dst[(size_t)row*NTOK + n] = s;
    }
}

// ---------------- K3: gram via mma.sync bf16 hi/lo split, DOUBLE-BUFFERED ----------------
// Dynamic smem: 4 arrays x 2 stages x [96][GP] bf16 = 61440 bytes.
#define GP 40
#define GSTAGE (96*GP)          // elems per stage per array
#define GSMEM_BYTES (4*2*GSTAGE*2)
__global__ void __launch_bounds__(256, 2) k_gram() {
    extern __shared__ __nv_bfloat16 gsm[];
    __nv_bfloat16* Qh = gsm;
    __nv_bfloat16* Ql = gsm + 2*GSTAGE;
    __nv_bfloat16* Kh = gsm + 4*GSTAGE;
    __nv_bfloat16* Kl = gsm + 6*GSTAGE;
    const int chunk = blockIdx.x, bh = blockIdx.y;
    const int tid = threadIdx.x, lane = tid & 31, w = tid >> 5;
    const int wm = w >> 2, wn = w & 3;
    const int n0 = chunk * (NTOK / NCHUNK);

    const float* Q  = g_q + (size_t)bh*CB*NTOK;
    const float* Kp = g_k + (size_t)bh*CB*NTOK;

    float acc[9][4];
#pragma unroll
    for (int t = 0; t < 9; ++t) { acc[t][0]=0.f; acc[t][1]=0.f; acc[t][2]=0.f; acc[t][3]=0.f; }
    float sq[12], sk[12];
#pragma unroll
    for (int t = 0; t < 12; ++t) { sq[t] = 0.f; sk[t] = 0.f; }

    float qr[12], kr[12];
#pragma unroll
    for (int t = 0; t < 12; ++t) {
        int r = w + 8*t;
        qr[t] = Q [(size_t)r*NTOK + n0 + lane];
        kr[t] = Kp[(size_t)r*NTOK + n0 + lane];
    }

    const int NIT = (NTOK / NCHUNK) / 32;   // 32
    for (int kt = 0; kt < NIT; ++kt) {
        const int st = (kt & 1) * GSTAGE;
        // store phase into stage st (overlaps other warps' mma on stage st^1)
#pragma unroll
        for (int t = 0; t < 12; ++t) {
            int r = w + 8*t;
            float qv = qr[t], kv = kr[t];
            __nv_bfloat16 qh = __float2bfloat16(qv);
            __nv_bfloat16 kh = __float2bfloat16(kv);
            Qh[st + r*GP + lane] = qh;
            Ql[st + r*GP + lane] = __float2bfloat16(qv - __bfloat162float(qh));
            Kh[st + r*GP + lane] = kh;
            Kl[st + r*GP + lane] = __float2bfloat16(kv - __bfloat162float(kh));
            sq[t] = fmaf(qv, qv, sq[t]);
            sk[t] = fmaf(kv, kv, sk[t]);
        }
        // prefetch next chunk while stores drain / before barrier
        if (kt + 1 < NIT) {
            int base = n0 + (kt + 1)*32 + lane;
#pragma unroll
            for (int t = 0; t < 12; ++t) {
                int r = w + 8*t;
                qr[t] = Q [(size_t)r*NTOK + base];
                kr[t] = Kp[(size_t)r*NTOK + base];
            }
        }
        __syncthreads();   // single barrier per iteration
#pragma unroll
        for (int ks = 0; ks < 2; ++ks) {
            const int k0 = ks*16;
            uint32_t ah[3][4], al[3][4], bhF[3][2], blF[3][2];
            const int arow = (lane & 15), acol = k0 + ((lane >> 4) << 3);
            const int brow = (lane & 7),  bcol = k0 + (((lane >> 3) & 1) << 3);
#pragma unroll
            for (int f = 0; f < 3; ++f) {
                int off = st + (wm*48 + f*16 + arow)*GP + acol;
                ldsm_x4(ah[f], cvta(&Qh[off]));
                ldsm_x4(al[f], cvta(&Ql[off]));
            }
#pragma unroll
            for (int g = 0; g < 3; ++g) {
                int off = st + (wn*24 + g*8 + brow)*GP + bcol;
                ldsm_x2(bhF[g], cvta(&Kh[off]));
                ldsm_x2(blF[g], cvta(&Kl[off]));
            }
#pragma unroll
            for (int f = 0; f < 3; ++f)
#pragma unroll
                for (int g = 0; g < 3; ++g) {
                    mma_bf16(acc[f*3+g], ah[f], bhF[g]);
                    mma_bf16(acc[f*3+g], ah[f], blF[g]);
                    mma_bf16(acc[f*3+g], al[f], bhF[g]);
                }
        }
    }
    float* Sp = g_Spart + ((size_t)bh*NCHUNK + chunk)*CB*CB;
#pragma unroll
    for (int f = 0; f < 3; ++f)
#pragma unroll
        for (int g = 0; g < 3; ++g) {
            int row = wm*48 + f*16 + (lane >> 2);
            int col = wn*24 + g*8 + (lane & 3)*2;
            float* c = acc[f*3+g];
            *(float2*)&Sp[row*CB + col]     = make_float2(c[0], c[1]);
            *(float2*)&Sp[(row+8)*CB + col] = make_float2(c[2], c[3]);
        }
#pragma unroll
    for (int t = 0; t < 12; ++t) {
        float s1 = sq[t], s2 = sk[t];
#pragma unroll
        for (int off = 16; off > 0; off >>= 1) {
            s1 += __shfl_xor_sync(0xffffffffu, s1, off);
            s2 += __shfl_xor_sync(0xffffffffu, s2, off);
        }
        if (lane == 0) {
            int r = w + 8*t;
            g_ssqpart[((0*BHTOT + bh)*NCHUNK + chunk)*CB + r] = s1;
            g_ssqpart[((1*BHTOT + bh)*NCHUNK + chunk)*CB + r] = s2;
        }
    }
}

// ---------------- K4: reduce + normalize + softmax ----------------
__global__ void k_soft(const float* __restrict__ temperature) {
    __shared__ float invk[96];
    __shared__ float invq[8];
    const int bh = blockIdx.y;
    const int rb = blockIdx.x * 8;
    const int head = bh & 7;
    const int tid = threadIdx.x;
    const int lane = tid & 31;
    const int w = tid >> 5;

    if (tid < 96) {
        float sumk = 0.f;
        for (int c = 0; c < NCHUNK; ++c)
            sumk += g_ssqpart[((1*BHTOT + bh)*NCHUNK + c)*CB + tid];
        invk[tid] = 1.f / fmaxf(sqrtf(sumk), 1e-12f);
    } else if (tid >= 128 && tid < 136) {
        int r = rb + tid - 128;
        float sumq = 0.f;
        for (int c = 0; c < NCHUNK; ++c)
            sumq += g_ssqpart[((0*BHTOT + bh)*NCHUNK + c)*CB + r];
        invq[tid - 128] = 1.f / fmaxf(sqrtf(sumq), 1e-12f);
    }
    __syncthreads();
    const float temp = temperature[head];
    const float* Sp = g_Spart + (size_t)bh*NCHUNK*CB*CB;
    float* Ao = g_attn + (size_t)bh*CB*CB;

    const int row = rb + w;
    float v[3];
#pragma unroll
    for (int j = 0; j < 3; ++j) {
        int col = lane + 32*j;
        float s = 0.f;
        for (int c = 0; c < NCHUNK; ++c) s += Sp[c*CB*CB + row*CB + col];
        v[j] = s * temp * invq[w] * invk[col];
    }
    float m = fmaxf(v[0], fmaxf(v[1], v[2]));
#pragma unroll
    for (int off = 16; off > 0; off >>= 1) m = fmaxf(m, __shfl_xor_sync(0xffffffffu, m, off));
    float e[3], sum = 0.f;
#pragma unroll
    for (int j = 0; j < 3; ++j) { e[j] = __expf(v[j] - m); sum += e[j]; }
#pragma unroll
    for (int off = 16; off > 0; off >>= 1) sum += __shfl_xor_sync(0xffffffffu, sum, off);
    float inv = 1.f / sum;
#pragma unroll
    for (int j = 0; j < 3; ++j) Ao[row*CB + lane + 32*j] = e[j] * inv;
}

// ---------------- K5: out = attn @ v via bf16-split mma (validated R11) ----------------
__global__ void __launch_bounds__(256, 2) k_av() {
    __shared__ __align__(16) char pool[92160];
    __nv_bfloat16* Ah = (__nv_bfloat16*)pool;
    __nv_bfloat16* Al = (__nv_bfloat16*)(pool + 19968);
    __nv_bfloat16* Vh = (__nv_bfloat16*)(pool + 39936);
    __nv_bfloat16* Vl = (__nv_bfloat16*)(pool + 66048);
    float* Os = (float*)(pool + 39936);
    const int nt = blockIdx.x, bh = blockIdx.y;
    const int b = bh >> 3, head = bh & 7;
    const int tid = threadIdx.x, lane = tid & 31, w = tid >> 5;
    const int wm = w >> 2, wn = w & 3;

    const float* A = g_attn + (size_t)bh*CB*CB;
    const float* V = g_v + (size_t)bh*CB*NTOK + nt*128;
    float4 as[9], vs[12];
#pragma unroll
    for (int t = 0; t < 9; ++t) {
        int i = tid + t*256;
        int r = i / 24, c = (i % 24) * 4;
        as[t] = *(const float4*)&A[r*CB + c];
    }
#pragma unroll
    for (int t = 0; t < 12; ++t) {
        int i = tid + t*256;
        int r = i >> 5, c4 = (i & 31) * 4;
        vs[t] = *(const float4*)&V[(size_t)r*NTOK + c4];
    }
#pragma unroll
    for (int t = 0; t < 9; ++t) {
        int i = tid + t*256;
        int r = i / 24, c = (i % 24) * 4;
        u64 hi, lo; split4(as[t], hi, lo);
        *(u64*)&Ah[r*104 + c] = hi;
        *(u64*)&Al[r*104 + c] = lo;
    }
#pragma unroll
    for (int t = 0; t < 12; ++t) {
        int i = tid + t*256;
        int r = i >> 5, c4 = (i & 31) * 4;
        u64 hi, lo; split4(vs[t], hi, lo);
        *(u64*)&Vh[r*136 + c4] = hi;
        *(u64*)&Vl[r*136 + c4] = lo;
    }
    __syncthreads();

    float acc[3][4][4];
#pragma unroll
    for (int f = 0; f < 3; ++f)
#pragma unroll
        for (int g = 0; g < 4; ++g)
#pragma unroll
            for (int t = 0; t < 4; ++t) acc[f][g][t] = 0.f;

#pragma unroll
    for (int ks = 0; ks < 6; ++ks) {
        uint32_t ah[3][4], al[3][4], bhf[4][2], blf[4][2];
        const int arow = lane & 15, acol = ks*16 + ((lane >> 4) << 3);
#pragma unroll
        for (int f = 0; f < 3; ++f) {
            int off = (wm*48 + f*16 + arow)*104 + acol;
            ldsm_x4(ah[f], cvta(&Ah[off]));
            ldsm_x4(al[f], cvta(&Al[off]));
        }
        const int brow = ks*16 + (lane & 15);
#pragma unroll
        for (int g = 0; g < 4; ++g) {
            int off = brow*136 + wn*32 + g*8;
            ldsm_x2t(bhf[g], cvta(&Vh[off]));
            ldsm_x2t(blf[g], cvta(&Vl[off]));
        }
#pragma unroll
        for (int f = 0; f < 3; ++f)
#pragma unroll
            for (int g = 0; g < 4; ++g) {
                mma_bf16(acc[f][g], ah[f], bhf[g]);
                mma_bf16(acc[f][g], ah[f], blf[g]);
                mma_bf16(acc[f][g], al[f], bhf[g]);
            }
    }
    __syncthreads();
#pragma unroll
    for (int f = 0; f < 3; ++f) {
        int row0 = wm*48 + f*16 + (lane >> 2);
#pragma unroll
        for (int g = 0; g < 4; ++g) {
            int col = wn*32 + g*8 + (lane & 3)*2;
            *(float2*)&Os[row0*132 + col]     = make_float2(acc[f][g][0], acc[f][g][1]);
            *(float2*)&Os[(row0+8)*132 + col] = make_float2(acc[f][g][2], acc[f][g][3]);
        }
    }
    __syncthreads();
    float* outb = g_out1 + (size_t)b*CIN*HW;
    for (int i = tid; i < 24*128; i += 256) {
        int group = i >> 7, n = i & 127;
        int ci = group >> 2, Nh = group & 3;
        int cb = ci*16 + Nh*4;
        float4 val = make_float4(Os[cb*132 + n], Os[(cb+1)*132 + n],
                                 Os[(cb+2)*132 + n], Os[(cb+3)*132 + n]);
        int ch = head*CSUB + ci;
        int y = nt*4 + Nh;
        *(float4*)&outb[((size_t)ch*HH + y)*WW + n*4] = val;
    }
}

// ---------------- launch ----------------
extern "C" void kernel_launch(void* const* d_in, const int* in_sizes, int n_in,
                              void* d_out, int out_size) {
    (void)in_sizes; (void)n_in; (void)out_size;
    const float* x      = (const float*)d_in[0];
    const float* qkv_w  = (const float*)d_in[1];
    const float* dw_w   = (const float*)d_in[2];
    const float* proj_w = (const float*)d_in[3];
    const float* temper = (const float*)d_in[4];
    float* out = (float*)d_out;

    static int attr_set = 0;
    if (!attr_set) {
        cudaFuncSetAttribute(k_gram, cudaFuncAttributeMaxDynamicSharedMemorySize, GSMEM_BYTES);
        attr_set = 1;
    }

    k_conv<<<dim3(3, HW/256, B_), 256>>>(x, qkv_w, nullptr, CQ, 0);
    k_dw  <<<dim3(8, 16, B_*CQ), 256>>>(dw_w);
    k_gram<<<dim3(NCHUNK, BHTOT), 256, GSMEM_BYTES>>>();
    k_soft<<<dim3(12, BHTOT), 256>>>(temper);
    k_av  <<<dim3(128, BHTOT), 256>>>();
    k_conv<<<dim3(1, HW/256, B_), 256>>>(nullptr, proj_w, out, CIN, 1);
}